// round 5
// baseline (speedup 1.0000x reference)
#include <cuda_runtime.h>
#include <cstdint>

#define D_DIM 768
#define OUT_DIM 196
#define TM 128
#define BK 32
#define NP 209      // W_sh row stride (209 % 32 = 17, coprime -> conflict-free)
#define XS 36       // xn_sh row stride (36 % 32 = 4 -> conflict-free A-frag loads)
#define NTILES (D_DIM / BK)   // 24
#define NFRAG 13    // n-fragments per warp (13*8 = 104 cols per warp-n slice)

__device__ __forceinline__ uint32_t f2tf32(float f) {
    uint32_t u;
    asm("cvt.rna.tf32.f32 %0, %1;" : "=r"(u) : "f"(f));
    return u;
}

__device__ __forceinline__ void mma_tf32(float* c, const uint32_t* a, const uint32_t* b) {
    asm volatile(
        "mma.sync.aligned.m16n8k8.row.col.f32.tf32.tf32.f32 "
        "{%0,%1,%2,%3}, {%4,%5,%6,%7}, {%8,%9}, {%0,%1,%2,%3};"
        : "+f"(c[0]), "+f"(c[1]), "+f"(c[2]), "+f"(c[3])
        : "r"(a[0]), "r"(a[1]), "r"(a[2]), "r"(a[3]), "r"(b[0]), "r"(b[1]));
}

__global__ __launch_bounds__(256, 1)
void ln_gemm_kernel(const float* __restrict__ x,
                    const float* __restrict__ gamma,
                    const float* __restrict__ beta,
                    const float* __restrict__ W,
                    const float* __restrict__ bias,
                    float* __restrict__ out)
{
    __shared__ float mean_sh[TM];
    __shared__ float rstd_sh[TM];
    __shared__ uint32_t xn_sh[TM * XS];    // 18432 B
    __shared__ uint32_t w_sh[BK * NP];     // 26752 B

    const int tid  = threadIdx.x;
    const int lane = tid & 31;
    const int wrp  = tid >> 5;             // 0..7
    const long long R0 = (long long)blockIdx.x * TM;

    // ---------------- Phase 1: per-row stats ----------------
    for (int rr = 0; rr < 16; rr++) {
        const int r = wrp * 16 + rr;
        const float* xp = x + (R0 + r) * D_DIM;
        float s = 0.f, s2 = 0.f;
        #pragma unroll
        for (int i = 0; i < 24; i++) {
            float v = xp[lane + 32 * i];
            s  += v;
            s2 += v * v;
        }
        #pragma unroll
        for (int off = 16; off; off >>= 1) {
            s  += __shfl_xor_sync(0xffffffffu, s,  off);
            s2 += __shfl_xor_sync(0xffffffffu, s2, off);
        }
        if (lane == 0) {
            float m   = s * (1.0f / D_DIM);
            float var = fmaxf(s2 * (1.0f / D_DIM) - m * m, 0.0f);
            mean_sh[r] = m;
            rstd_sh[r] = rsqrtf(var + 1e-6f);
        }
    }

    // Zero-pad W_sh columns n = 196..208 once (never overwritten later)
    for (int idx = tid; idx < 13 * 32; idx += 256) {
        int kk = idx & 31;
        int n  = 196 + (idx >> 5);
        w_sh[kk * NP + n] = 0u;
    }
    __syncthreads();

    // ---------------- Phase 2: fused normalize + GEMM ----------------
    const int warp_m = wrp & 3;     // 0..3 : rows warp_m*32 .. +31
    const int warp_n = wrp >> 2;    // 0..1 : n-frags warp_n*13 ..
    const int grp = lane >> 2;      // 0..7
    const int tig = lane & 3;       // 0..3
    const int nf0 = warp_n * 13;

    float acc[2][NFRAG][4];
    #pragma unroll
    for (int s = 0; s < 2; s++)
        #pragma unroll
        for (int j = 0; j < NFRAG; j++)
            #pragma unroll
            for (int q = 0; q < 4; q++) acc[s][j][q] = 0.f;

    const int xrow = wrp;   // load-phase row group (tid/32)
    const int xkk  = lane;  // load-phase k offset (tid%32)

    for (int kt = 0; kt < NTILES; kt++) {
        const int kbase = kt * BK;
        if (kt) __syncthreads();

        // x tile: load, normalize, convert to tf32, stage in shared
        const float g  = gamma[kbase + xkk];
        const float bt = beta[kbase + xkk];
        #pragma unroll
        for (int i = 0; i < 16; i++) {
            int r = xrow + i * 8;
            float xv = x[(R0 + r) * D_DIM + kbase + xkk];
            float v  = (xv - mean_sh[r]) * rstd_sh[r];
            v = v * g + bt;
            xn_sh[r * XS + xkk] = f2tf32(v);
        }

        // W tile: [OUT x BK] from global, transposed into shared [k][n]
        for (int idx = tid; idx < OUT_DIM * BK; idx += 256) {
            int n  = idx >> 5;
            int kk = idx & 31;
            w_sh[kk * NP + n] = f2tf32(W[n * D_DIM + kbase + kk]);
        }
        __syncthreads();

        // MMA over the 32-deep K tile (4 k-steps of 8)
        #pragma unroll
        for (int ks = 0; ks < 4; ks++) {
            uint32_t a[2][4];
            #pragma unroll
            for (int s = 0; s < 2; s++) {
                int mrow = warp_m * 32 + s * 16 + grp;
                int kc   = ks * 8 + tig;
                a[s][0] = xn_sh[mrow * XS + kc];
                a[s][1] = xn_sh[(mrow + 8) * XS + kc];
                a[s][2] = xn_sh[mrow * XS + kc + 4];
                a[s][3] = xn_sh[(mrow + 8) * XS + kc + 4];
            }
            #pragma unroll
            for (int j = 0; j < NFRAG; j++) {
                int nb = (nf0 + j) * 8 + grp;
                uint32_t b[2];
                b[0] = w_sh[(ks * 8 + tig)     * NP + nb];
                b[1] = w_sh[(ks * 8 + tig + 4) * NP + nb];
                mma_tf32(acc[0][j], a[0], b);
                mma_tf32(acc[1][j], a[1], b);
            }
        }
    }

    // ---------------- Epilogue: +bias, store ----------------
    #pragma unroll
    for (int s = 0; s < 2; s++) {
        #pragma unroll
        for (int j = 0; j < NFRAG; j++) {
            int n = (nf0 + j) * 8 + 2 * tig;
            if (n < OUT_DIM) {   // n even, OUT even -> pair (n, n+1) both valid
                float b0 = bias[n];
                float b1 = bias[n + 1];
                long long row0 = R0 + warp_m * 32 + s * 16 + grp;
                float2 v0 = make_float2(acc[s][j][0] + b0, acc[s][j][1] + b1);
                float2 v1 = make_float2(acc[s][j][2] + b0, acc[s][j][3] + b1);
                *reinterpret_cast<float2*>(out + row0 * OUT_DIM + n)       = v0;
                *reinterpret_cast<float2*>(out + (row0 + 8) * OUT_DIM + n) = v1;
            }
        }
    }
}

extern "C" void kernel_launch(void* const* d_in, const int* in_sizes, int n_in,
                              void* d_out, int out_size) {
    const float* x     = (const float*)d_in[0];
    const float* gamma = (const float*)d_in[1];
    const float* beta  = (const float*)d_in[2];
    const float* W     = (const float*)d_in[3];
    const float* b     = (const float*)d_in[4];
    float* out = (float*)d_out;

    const int rows = in_sizes[0] / D_DIM;   // 65536
    ln_gemm_kernel<<<rows / TM, 256>>>(x, gamma, beta, W, b, out);
}

// round 6
// speedup vs baseline: 3.0350x; 3.0350x over previous
#include <cuda_runtime.h>
#include <cstdint>

#define D_DIM 768
#define OUT_DIM 196
#define TM 128
#define BK 32
#define STAGES 3
#define NFRAG 13
#define NTILES (D_DIM / BK)          // 24
#define XSTRIDE 36                   // row stride (words) -> conflict-free frag reads
#define XB (TM * XSTRIDE)            // 4608 words / stage
#define WROWS 208                    // 196 padded to 208 (13 frags * 8 * 2 slices)
#define WB (WROWS * XSTRIDE)         // 7488 words / stage
#define SMEM_WORDS (STAGES * XB + STAGES * WB + 128 + 128 + 208 + 208)
#define SMEM_BYTES (SMEM_WORDS * 4)  // 147840

__device__ float g_wp[OUT_DIM * D_DIM];  // gamma-folded, tf32-rounded W
__device__ float g_sp[OUT_DIM];          // row sums of g_wp
__device__ float g_cb[OUT_DIM];          // beta.W + bias

__device__ __forceinline__ uint32_t f2tf32(float f) {
    uint32_t u;
    asm("cvt.rna.tf32.f32 %0, %1;" : "=r"(u) : "f"(f));
    return u;
}

__device__ __forceinline__ void mma_tf32(float* c, const uint32_t* a, const uint32_t* b) {
    asm volatile(
        "mma.sync.aligned.m16n8k8.row.col.f32.tf32.tf32.f32 "
        "{%0,%1,%2,%3}, {%4,%5,%6,%7}, {%8,%9}, {%0,%1,%2,%3};"
        : "+f"(c[0]), "+f"(c[1]), "+f"(c[2]), "+f"(c[3])
        : "r"(a[0]), "r"(a[1]), "r"(a[2]), "r"(a[3]), "r"(b[0]), "r"(b[1]));
}

__device__ __forceinline__ void cp16(float* dst, const float* src) {
    uint32_t d = (uint32_t)__cvta_generic_to_shared(dst);
    asm volatile("cp.async.cg.shared.global [%0], [%1], 16;" :: "r"(d), "l"(src));
}

// ---------------- Prologue: fold gamma into W, precompute sums ----------------
__global__ void prep_kernel(const float* __restrict__ W,
                            const float* __restrict__ gamma,
                            const float* __restrict__ beta,
                            const float* __restrict__ bias)
{
    __shared__ float rs[24], rc[24];
    const int n = blockIdx.x;
    const int k = threadIdx.x;          // 0..767
    const int lane = k & 31, wid = k >> 5;

    float w  = W[n * D_DIM + k];
    float wp = __uint_as_float(f2tf32(w * gamma[k]));   // tf32-rounded value
    g_wp[n * D_DIM + k] = wp;

    float s1 = wp;
    float cb = beta[k] * w;
    #pragma unroll
    for (int off = 16; off; off >>= 1) {
        s1 += __shfl_xor_sync(0xffffffffu, s1, off);
        cb += __shfl_xor_sync(0xffffffffu, cb, off);
    }
    if (lane == 0) { rs[wid] = s1; rc[wid] = cb; }
    __syncthreads();
    if (k < 32) {
        float a = (k < 24) ? rs[k] : 0.f;
        float c = (k < 24) ? rc[k] : 0.f;
        #pragma unroll
        for (int off = 16; off; off >>= 1) {
            a += __shfl_xor_sync(0xffffffffu, a, off);
            c += __shfl_xor_sync(0xffffffffu, c, off);
        }
        if (k == 0) { g_sp[n] = a; g_cb[n] = c + bias[n]; }
    }
}

// ---------------- Main: pipelined raw-x GEMM + in-pipeline stats ----------------
__global__ __launch_bounds__(256, 1)
void ln_gemm_kernel(const float* __restrict__ x, float* __restrict__ out)
{
    extern __shared__ float smem[];
    float* xbuf    = smem;                       // STAGES * XB
    float* wbuf    = smem + STAGES * XB;         // STAGES * WB
    float* mean_sh = wbuf + STAGES * WB;         // 128
    float* rstd_sh = mean_sh + 128;              // 128
    float* sp_sh   = rstd_sh + 128;              // 208
    float* cb_sh   = sp_sh + 208;                // 208

    const int tid  = threadIdx.x;
    const int lane = tid & 31;
    const int wrp  = tid >> 5;
    const long long R0 = (long long)blockIdx.x * TM;

    const int warp_m = wrp & 3;
    const int warp_n = wrp >> 2;
    const int grp = lane >> 2;
    const int tig = lane & 3;
    const int nf0 = warp_n * NFRAG;

    // Zero W pad rows (n = 196..207) in all stages; load S'/cb into smem
    for (int idx = tid; idx < STAGES * 12 * XSTRIDE; idx += 256) {
        int st = idx / (12 * XSTRIDE);
        int r  = idx % (12 * XSTRIDE);
        wbuf[st * WB + OUT_DIM * XSTRIDE + r] = 0.f;
    }
    if (tid < OUT_DIM) { sp_sh[tid] = g_sp[tid]; cb_sh[tid] = g_cb[tid]; }

    // Prefetch stages 0..2
    #pragma unroll
    for (int p = 0; p < STAGES; p++) {
        const int kbase = p * BK;
        #pragma unroll
        for (int i = 0; i < 4; i++) {
            int idx = tid + i * 256;        // 1024 chunks of 16B
            int r = idx >> 3, c = idx & 7;
            cp16(&xbuf[p * XB + r * XSTRIDE + c * 4],
                 x + (R0 + r) * D_DIM + kbase + c * 4);
        }
        #pragma unroll
        for (int i = 0; i < 7; i++) {
            int idx = tid + i * 256;        // 1568 chunks of 16B
            if (idx < OUT_DIM * 8) {
                int n = idx >> 3, c = idx & 7;
                cp16(&wbuf[p * WB + n * XSTRIDE + c * 4],
                     g_wp + n * D_DIM + kbase + c * 4);
            }
        }
        asm volatile("cp.async.commit_group;");
    }

    float acc[2][NFRAG][4];
    #pragma unroll
    for (int s = 0; s < 2; s++)
        #pragma unroll
        for (int j = 0; j < NFRAG; j++)
            #pragma unroll
            for (int q = 0; q < 4; q++) acc[s][j][q] = 0.f;

    float ss = 0.f, ss2 = 0.f;               // per-thread stats partials
    const int srow = tid >> 1;
    const int soff = (tid & 1) * 16;

    for (int kt = 0; kt < NTILES; kt++) {
        const int st = kt % STAGES;
        asm volatile("cp.async.wait_group %0;" :: "n"(STAGES - 1));
        __syncthreads();

        const float* xs = &xbuf[st * XB];
        const float* ws = &wbuf[st * WB];

        // In-pipeline stats (raw x, fp32 exact)
        {
            const float* xp = xs + srow * XSTRIDE + soff;
            #pragma unroll
            for (int i = 0; i < 4; i++) {
                float4 v = *reinterpret_cast<const float4*>(xp + i * 4);
                ss  += (v.x + v.y) + (v.z + v.w);
                ss2 += v.x * v.x + v.y * v.y + v.z * v.z + v.w * v.w;
            }
        }

        // MMA over 4 k-steps of 8
        #pragma unroll
        for (int ks = 0; ks < 4; ks++) {
            uint32_t a[2][4];
            const int kc = ks * 8 + tig;
            #pragma unroll
            for (int s = 0; s < 2; s++) {
                int mrow = warp_m * 32 + s * 16 + grp;
                a[s][0] = f2tf32(xs[mrow * XSTRIDE + kc]);
                a[s][1] = f2tf32(xs[(mrow + 8) * XSTRIDE + kc]);
                a[s][2] = f2tf32(xs[mrow * XSTRIDE + kc + 4]);
                a[s][3] = f2tf32(xs[(mrow + 8) * XSTRIDE + kc + 4]);
            }
            #pragma unroll
            for (int j = 0; j < NFRAG; j++) {
                int nb = (nf0 + j) * 8 + grp;
                uint32_t b[2];
                b[0] = __float_as_uint(ws[nb * XSTRIDE + kc]);
                b[1] = __float_as_uint(ws[nb * XSTRIDE + kc + 4]);
                mma_tf32(acc[0][j], a[0], b);
                mma_tf32(acc[1][j], a[1], b);
            }
        }
        __syncthreads();

        // Refill this stage with tile kt+STAGES
        const int knext = kt + STAGES;
        if (knext < NTILES) {
            const int kbase = knext * BK;
            #pragma unroll
            for (int i = 0; i < 4; i++) {
                int idx = tid + i * 256;
                int r = idx >> 3, c = idx & 7;
                cp16(&xbuf[st * XB + r * XSTRIDE + c * 4],
                     x + (R0 + r) * D_DIM + kbase + c * 4);
            }
            #pragma unroll
            for (int i = 0; i < 7; i++) {
                int idx = tid + i * 256;
                if (idx < OUT_DIM * 8) {
                    int n = idx >> 3, c = idx & 7;
                    cp16(&wbuf[st * WB + n * XSTRIDE + c * 4],
                         g_wp + n * D_DIM + kbase + c * 4);
                }
            }
        }
        asm volatile("cp.async.commit_group;");
    }

    // Finalize stats: pair (tid, tid^1) holds the two k-halves of row tid>>1
    float stot  = ss  + __shfl_xor_sync(0xffffffffu, ss,  1);
    float stot2 = ss2 + __shfl_xor_sync(0xffffffffu, ss2, 1);
    if ((tid & 1) == 0) {
        int r = tid >> 1;
        float m   = stot * (1.0f / D_DIM);
        float var = fmaxf(stot2 * (1.0f / D_DIM) - m * m, 0.0f);
        mean_sh[r] = m;
        rstd_sh[r] = rsqrtf(var + 1e-6f);
    }
    __syncthreads();

    // Epilogue: out = rstd*(acc - mean*S') + cb
    #pragma unroll
    for (int s = 0; s < 2; s++) {
        const int mrow = warp_m * 32 + s * 16 + grp;
        const float mu0 = mean_sh[mrow],     rs0 = rstd_sh[mrow];
        const float mu1 = mean_sh[mrow + 8], rs1 = rstd_sh[mrow + 8];
        #pragma unroll
        for (int j = 0; j < NFRAG; j++) {
            int n = (nf0 + j) * 8 + 2 * tig;
            if (n < OUT_DIM) {
                float sp0 = sp_sh[n],  sp1 = sp_sh[n + 1];
                float cb0 = cb_sh[n],  cb1 = cb_sh[n + 1];
                long long row0 = R0 + mrow;
                float2 v0 = make_float2(rs0 * (acc[s][j][0] - mu0 * sp0) + cb0,
                                        rs0 * (acc[s][j][1] - mu0 * sp1) + cb1);
                float2 v1 = make_float2(rs1 * (acc[s][j][2] - mu1 * sp0) + cb0,
                                        rs1 * (acc[s][j][3] - mu1 * sp1) + cb1);
                *reinterpret_cast<float2*>(out + row0 * OUT_DIM + n)       = v0;
                *reinterpret_cast<float2*>(out + (row0 + 8) * OUT_DIM + n) = v1;
            }
        }
    }
}

extern "C" void kernel_launch(void* const* d_in, const int* in_sizes, int n_in,
                              void* d_out, int out_size) {
    const float* x     = (const float*)d_in[0];
    const float* gamma = (const float*)d_in[1];
    const float* beta  = (const float*)d_in[2];
    const float* W     = (const float*)d_in[3];
    const float* b     = (const float*)d_in[4];
    float* out = (float*)d_out;

    cudaFuncSetAttribute(ln_gemm_kernel,
                         cudaFuncAttributeMaxDynamicSharedMemorySize, SMEM_BYTES);

    const int rows = in_sizes[0] / D_DIM;   // 65536
    prep_kernel<<<OUT_DIM, D_DIM>>>(W, gamma, beta, b);
    ln_gemm_kernel<<<rows / TM, 256, SMEM_BYTES>>>(x, out);
}